// round 2
// baseline (speedup 1.0000x reference)
#include <cuda_runtime.h>
#include <cuda_bf16.h>
#include <math.h>

#define BB 64
#define VV 16384
#define EE 524288
#define KCH 6
#define F1 32
#define FC1FIN 65536

// ---------------- device scratch ----------------
__device__ float g_xs[6 * VV * BB];        // cheby basis [k][v][b]
__device__ float g_pooled[BB * FC1FIN];    // [b][vp*32+f]
__device__ float g_svals[EE];
__device__ int   g_scols[EE];
__device__ int   g_counts[VV];
__device__ int   g_cursor[VV];
__device__ int   g_rowstart[VV + 1];
__device__ float g_xd[BB * 512];
__device__ float g_xn1[BB * 1024];
__device__ float g_xn[BB * 512];

// ---------------- helpers ----------------
__device__ __forceinline__ unsigned f2tf(float x) {
    unsigned r;
    asm("cvt.rna.tf32.f32 %0, %1;" : "=r"(r) : "f"(x));
    return r;
}

__device__ __forceinline__ void mma_tf32(float c[4], unsigned a0, unsigned a1,
                                         unsigned a2, unsigned a3,
                                         unsigned b0, unsigned b1) {
    asm volatile(
        "mma.sync.aligned.m16n8k8.row.col.f32.tf32.tf32.f32 "
        "{%0,%1,%2,%3},{%4,%5,%6,%7},{%8,%9},{%0,%1,%2,%3};"
        : "+f"(c[0]), "+f"(c[1]), "+f"(c[2]), "+f"(c[3])
        : "r"(a0), "r"(a1), "r"(a2), "r"(a3), "r"(b0), "r"(b1));
}

// ---------------- transpose x_in [B,V] -> xs[0] [V,B] ----------------
__global__ void k_transpose(const float* __restrict__ in, float* __restrict__ out) {
    __shared__ float tile[32][33];
    int vx = blockIdx.x * 32 + threadIdx.x;
    int by = blockIdx.y * 32;
    for (int i = threadIdx.y; i < 32; i += 8)
        tile[i][threadIdx.x] = in[(by + i) * VV + vx];
    __syncthreads();
    for (int i = threadIdx.y; i < 32; i += 8)
        out[(blockIdx.x * 32 + i) * BB + by + threadIdx.x] = tile[threadIdx.x][i];
}

// ---------------- CSR build ----------------
__global__ void k_hist(const int* __restrict__ rows) {
    int e = blockIdx.x * 256 + threadIdx.x;
    if (e < EE) atomicAdd(&g_counts[rows[e]], 1);
}

__global__ void k_scan() {
    __shared__ int warp_sums[16];
    int t = threadIdx.x;
    int base = t * 32;
    int local[32];
    int s = 0;
#pragma unroll
    for (int i = 0; i < 32; i++) local[i] = g_counts[base + i];
#pragma unroll
    for (int i = 0; i < 32; i++) { int v = local[i]; local[i] = s; s += v; }
    int lane = t & 31, warp = t >> 5;
    int x = s;
#pragma unroll
    for (int off = 1; off < 32; off <<= 1) {
        int y = __shfl_up_sync(0xffffffffu, x, off);
        if (lane >= off) x += y;
    }
    if (lane == 31) warp_sums[warp] = x;
    __syncthreads();
    if (warp == 0 && lane < 16) {
        int y = warp_sums[lane];
#pragma unroll
        for (int off = 1; off < 16; off <<= 1) {
            int z = __shfl_up_sync(0x0000ffffu, y, off);
            if (lane >= off) y += z;
        }
        warp_sums[lane] = y;
    }
    __syncthreads();
    int prefix = x - s + (warp ? warp_sums[warp - 1] : 0);
#pragma unroll
    for (int i = 0; i < 32; i++) g_rowstart[base + i] = prefix + local[i];
    if (t == 511) g_rowstart[VV] = prefix + s;
}

__global__ void k_scatter(const int* __restrict__ rows, const int* __restrict__ cols,
                          const float* __restrict__ vals) {
    int e = blockIdx.x * 256 + threadIdx.x;
    if (e < EE) {
        int r = rows[e];
        int pos = g_rowstart[r] + atomicAdd(&g_cursor[r], 1);
        g_scols[pos] = cols[e];
        g_svals[pos] = vals[e];
    }
}

// ---------------- SpMM (CSR, warp per row) ----------------
// dst[row][:] = c * (L @ src)[row][:] - (prev ? prev[row][:] : 0)
__global__ void k_spmm(const float* __restrict__ src, const float* __restrict__ prev,
                       float* __restrict__ dst, float c) {
    int warp = threadIdx.x >> 5, lane = threadIdx.x & 31;
    int row = blockIdx.x * 8 + warp;
    int s = g_rowstart[row], e = g_rowstart[row + 1];
    float a0 = 0.f, a1 = 0.f;
    for (int i = s; i < e; i++) {
        float v = g_svals[i];
        int col = g_scols[i];
        const float* p = src + col * BB;
        a0 += v * p[lane];
        a1 += v * p[lane + 32];
    }
    float p0 = prev ? prev[row * BB + lane] : 0.f;
    float p1 = prev ? prev[row * BB + lane + 32] : 0.f;
    dst[row * BB + lane]      = c * a0 - p0;
    dst[row * BB + lane + 32] = c * a1 - p1;
}

// ---------------- cheby combine + relu + maxpool(8) ----------------
__global__ void k_cheby(const float* __restrict__ w, const float* __restrict__ bias) {
    __shared__ float tile[6][8][64];
    int vp = blockIdx.x;
    int t = threadIdx.x;
    for (int idx = t; idx < 6 * 8 * 64; idx += 256) {
        int k = idx >> 9;
        int rem = idx & 511;
        int p = rem >> 6;
        int b = rem & 63;
        tile[k][p][b] = g_xs[k * (VV * BB) + (vp * 8 + p) * BB + b];
    }
    __syncthreads();
    int f = t & 31, bg = t >> 5;
    float wr[6];
#pragma unroll
    for (int k = 0; k < 6; k++) wr[k] = w[f * 6 + k];
    float bf = bias[f];
    for (int bb = 0; bb < 8; bb++) {
        int b = bg * 8 + bb;
        float m = -1e30f;
#pragma unroll
        for (int p = 0; p < 8; p++) {
            float s = bf;
#pragma unroll
            for (int k = 0; k < 6; k++) s += tile[k][p][b] * wr[k];
            m = fmaxf(m, s);
        }
        g_pooled[b * FC1FIN + vp * 32 + f] = fmaxf(m, 0.f);
    }
}

// ---------------- GEMM helpers ----------------
__global__ void k_initbias(float* __restrict__ C, const float* __restrict__ bias, int N) {
    int i = blockIdx.x * 256 + threadIdx.x;  // i = b*N + j
    C[i] = bias[i % N];
}

__global__ void k_relu(float* __restrict__ C) {
    int i = blockIdx.x * 256 + threadIdx.x;
    C[i] = fmaxf(C[i], 0.f);
}

// C[64,N] += A[64,K] * W[N,K]^T   (split-K via grid.y, atomic accumulate)
__global__ void k_gemm(const float* __restrict__ A, const float* __restrict__ W,
                       float* __restrict__ C, int K, int N, int kchunk) {
    __shared__ unsigned As[64][36];
    __shared__ unsigned Ws[64][36];
    int t = threadIdx.x;
    int lane = t & 31, warp = t >> 5;
    int jt = blockIdx.x * 64;
    int k0 = blockIdx.y * kchunk;
    int kend = k0 + kchunk;
    int bq = warp & 3;   // b-row block (*16)
    int jh = warp >> 2;  // j-col block (*32)
    float acc[4][4] = {};
    for (int kt = k0; kt < kend; kt += 32) {
#pragma unroll
        for (int rr = 0; rr < 2; rr++) {
            int idx = t + rr * 256;      // 0..511
            int row = idx >> 3, q = idx & 7;
            float4 va = *reinterpret_cast<const float4*>(&A[row * K + kt + q * 4]);
            As[row][q * 4 + 0] = f2tf(va.x);
            As[row][q * 4 + 1] = f2tf(va.y);
            As[row][q * 4 + 2] = f2tf(va.z);
            As[row][q * 4 + 3] = f2tf(va.w);
            float4 vw = *reinterpret_cast<const float4*>(&W[(jt + row) * K + kt + q * 4]);
            Ws[row][q * 4 + 0] = f2tf(vw.x);
            Ws[row][q * 4 + 1] = f2tf(vw.y);
            Ws[row][q * 4 + 2] = f2tf(vw.z);
            Ws[row][q * 4 + 3] = f2tf(vw.w);
        }
        __syncthreads();
#pragma unroll
        for (int ks = 0; ks < 4; ks++) {
            int kk = ks * 8;
            unsigned a0 = As[bq * 16 + (lane >> 2)][kk + (lane & 3)];
            unsigned a1 = As[bq * 16 + (lane >> 2) + 8][kk + (lane & 3)];
            unsigned a2 = As[bq * 16 + (lane >> 2)][kk + (lane & 3) + 4];
            unsigned a3 = As[bq * 16 + (lane >> 2) + 8][kk + (lane & 3) + 4];
#pragma unroll
            for (int nf = 0; nf < 4; nf++) {
                int nrow = jh * 32 + nf * 8 + (lane >> 2);
                unsigned b0 = Ws[nrow][kk + (lane & 3)];
                unsigned b1 = Ws[nrow][kk + (lane & 3) + 4];
                mma_tf32(acc[nf], a0, a1, a2, a3, b0, b1);
            }
        }
        __syncthreads();
    }
    int r0 = bq * 16 + (lane >> 2);
#pragma unroll
    for (int nf = 0; nf < 4; nf++) {
        int c0 = jt + jh * 32 + nf * 8 + 2 * (lane & 3);
        atomicAdd(&C[r0 * N + c0],           acc[nf][0]);
        atomicAdd(&C[r0 * N + c0 + 1],       acc[nf][1]);
        atomicAdd(&C[(r0 + 8) * N + c0],     acc[nf][2]);
        atomicAdd(&C[(r0 + 8) * N + c0 + 1], acc[nf][3]);
    }
}

// ---------------- sum2 + log_softmax ----------------
__global__ void k_sum2(const float* __restrict__ xh, const float* __restrict__ xn,
                       const float* __restrict__ w, const float* __restrict__ bias,
                       float* __restrict__ out) {
    int b = blockIdx.x;
    int t = threadIdx.x, lane = t & 31, warp = t >> 5;
    __shared__ float red[10];
    for (int o = warp; o < 10; o += 8) {
        float p = 0.f;
        for (int k = lane; k < 1024; k += 32) {
            float xv = (k < 512) ? xh[b * 512 + k] : xn[b * 512 + k - 512];
            p += xv * w[o * 1024 + k];
        }
#pragma unroll
        for (int off = 16; off; off >>= 1) p += __shfl_down_sync(0xffffffffu, p, off);
        if (lane == 0) red[o] = p + bias[o];
    }
    __syncthreads();
    if (t == 0) {
        float m = -1e30f;
        for (int o = 0; o < 10; o++) m = fmaxf(m, red[o]);
        float s = 0.f;
        for (int o = 0; o < 10; o++) s += expf(red[o] - m);
        float lse = m + logf(s);
        for (int o = 0; o < 10; o++) out[b * 10 + o] = red[o] - lse;
    }
}

// ---------------- launch ----------------
extern "C" void kernel_launch(void* const* d_in, const int* in_sizes, int n_in,
                              void* d_out, int out_size) {
    const float* x_in   = (const float*)d_in[0];
    const float* L_vals = (const float*)d_in[1];
    const float* cl1_w  = (const float*)d_in[2];
    const float* cl1_b  = (const float*)d_in[3];
    const float* fc1_w  = (const float*)d_in[4];
    const float* fc1_b  = (const float*)d_in[5];
    const float* fc2_w  = (const float*)d_in[6];
    const float* fc2_b  = (const float*)d_in[7];
    const float* fc3_w  = (const float*)d_in[8];
    const float* fc3_b  = (const float*)d_in[9];
    const float* nn1_w  = (const float*)d_in[10];
    const float* nn1_b  = (const float*)d_in[11];
    const float* nn2_w  = (const float*)d_in[12];
    const float* nn2_b  = (const float*)d_in[13];
    const float* sum2_w = (const float*)d_in[14];
    const float* sum2_b = (const float*)d_in[15];
    const int*   L_rows = (const int*)d_in[16];
    const int*   L_cols = (const int*)d_in[17];

    float* out = (float*)d_out;
    float* out_dec = out;                    // [64,16384]
    float* out_hid = out + 64 * 16384;       // [64,512]
    float* out_lp  = out_hid + 64 * 512;     // [64,10]

    float* xs;     cudaGetSymbolAddress((void**)&xs, g_xs);
    float* pooled; cudaGetSymbolAddress((void**)&pooled, g_pooled);
    int*   counts; cudaGetSymbolAddress((void**)&counts, g_counts);
    int*   cursor; cudaGetSymbolAddress((void**)&cursor, g_cursor);
    float* xd;     cudaGetSymbolAddress((void**)&xd, g_xd);
    float* xn1;    cudaGetSymbolAddress((void**)&xn1, g_xn1);
    float* xn;     cudaGetSymbolAddress((void**)&xn, g_xn);

    const int VB = VV * BB;

    // x0 = x_in^T
    k_transpose<<<dim3(VV / 32, 2), dim3(32, 8)>>>(x_in, xs);

    // CSR build
    cudaMemsetAsync(counts, 0, VV * sizeof(int));
    cudaMemsetAsync(cursor, 0, VV * sizeof(int));
    k_hist<<<EE / 256, 256>>>(L_rows);
    k_scan<<<1, 512>>>();
    k_scatter<<<EE / 256, 256>>>(L_rows, L_cols, L_vals);

    // cheby recurrence
    k_spmm<<<VV / 8, 256>>>(xs, nullptr, xs + VB, 1.f);
    for (int k = 2; k < KCH; k++)
        k_spmm<<<VV / 8, 256>>>(xs + (k - 1) * VB, xs + (k - 2) * VB, xs + k * VB, 2.f);

    // conv-combine + relu + maxpool -> pooled [64][65536]
    k_cheby<<<VV / 8, 256>>>(cl1_w, cl1_b);

    // fc1 -> x_hidden (in d_out)
    k_initbias<<<64 * 512 / 256, 256>>>(out_hid, fc1_b, 512);
    k_gemm<<<dim3(512 / 64, 32), 256>>>(pooled, fc1_w, out_hid, 65536, 512, 2048);
    k_relu<<<64 * 512 / 256, 256>>>(out_hid);

    // nn1 -> xn1
    k_initbias<<<64 * 1024 / 256, 256>>>(xn1, nn1_b, 1024);
    k_gemm<<<dim3(1024 / 64, 16), 256>>>(x_in, nn1_w, xn1, 16384, 1024, 1024);
    k_relu<<<64 * 1024 / 256, 256>>>(xn1);

    // fc2 -> xd
    k_initbias<<<64 * 512 / 256, 256>>>(xd, fc2_b, 512);
    k_gemm<<<dim3(512 / 64, 4), 256>>>(out_hid, fc2_w, xd, 512, 512, 128);
    k_relu<<<64 * 512 / 256, 256>>>(xd);

    // nn2 -> xn
    k_initbias<<<64 * 512 / 256, 256>>>(xn, nn2_b, 512);
    k_gemm<<<dim3(512 / 64, 8), 256>>>(xn1, nn2_w, xn, 1024, 512, 128);
    k_relu<<<64 * 512 / 256, 256>>>(xn);

    // fc3 -> x_decode (in d_out)
    k_initbias<<<64 * 16384 / 256, 256>>>(out_dec, fc3_b, 16384);
    k_gemm<<<dim3(16384 / 64, 1), 256>>>(xd, fc3_w, out_dec, 512, 16384, 512);

    // sum2 + log_softmax
    k_sum2<<<64, 256>>>(out_hid, xn, sum2_w, sum2_b, out_lp);
}

// round 3
// speedup vs baseline: 1.3287x; 1.3287x over previous
#include <cuda_runtime.h>
#include <cuda_bf16.h>
#include <math.h>

#define BB 64
#define VV 16384
#define EE 524288
#define KCH 6
#define FC1FIN 65536

// ---------------- device scratch ----------------
__device__ float g_xs[6 * VV * BB];        // cheby basis [k][v][b]
__device__ float g_pooled[BB * FC1FIN];    // [b][vp*32+f]
__device__ int2  g_edges[EE];              // packed {col, val_bits}
__device__ int   g_counts[VV];
__device__ int   g_cursor[VV];
__device__ int   g_rowstart[VV + 1];
__device__ float g_xd[BB * 512];
__device__ float g_xn1[BB * 1024];
__device__ float g_xn[BB * 512];

// ---------------- helpers ----------------
__device__ __forceinline__ unsigned f2tf(float x) {
    unsigned r;
    asm("cvt.rna.tf32.f32 %0, %1;" : "=r"(r) : "f"(x));
    return r;
}

__device__ __forceinline__ void mma_tf32(float c[4], unsigned a0, unsigned a1,
                                         unsigned a2, unsigned a3,
                                         unsigned b0, unsigned b1) {
    asm volatile(
        "mma.sync.aligned.m16n8k8.row.col.f32.tf32.tf32.f32 "
        "{%0,%1,%2,%3},{%4,%5,%6,%7},{%8,%9},{%0,%1,%2,%3};"
        : "+f"(c[0]), "+f"(c[1]), "+f"(c[2]), "+f"(c[3])
        : "r"(a0), "r"(a1), "r"(a2), "r"(a3), "r"(b0), "r"(b1));
}

// ---------------- transpose x_in [B,V] -> xs[0] [V,B] ----------------
__global__ void k_transpose(const float* __restrict__ in, float* __restrict__ out) {
    __shared__ float tile[32][33];
    int vx = blockIdx.x * 32 + threadIdx.x;
    int by = blockIdx.y * 32;
    for (int i = threadIdx.y; i < 32; i += 8)
        tile[i][threadIdx.x] = in[(by + i) * VV + vx];
    __syncthreads();
    for (int i = threadIdx.y; i < 32; i += 8)
        out[(blockIdx.x * 32 + i) * BB + by + threadIdx.x] = tile[threadIdx.x][i];
}

// ---------------- CSR build ----------------
__global__ void k_hist(const int* __restrict__ rows) {
    int e = (blockIdx.x * 256 + threadIdx.x) * 2;
    int2 r = *reinterpret_cast<const int2*>(&rows[e]);
    atomicAdd(&g_counts[r.x], 1);
    atomicAdd(&g_counts[r.y], 1);
}

__global__ void k_scan() {
    __shared__ int warp_sums[16];
    int t = threadIdx.x;
    int base = t * 32;
    int local[32];
    int s = 0;
#pragma unroll
    for (int i = 0; i < 32; i++) local[i] = g_counts[base + i];
#pragma unroll
    for (int i = 0; i < 32; i++) { int v = local[i]; local[i] = s; s += v; }
    int lane = t & 31, warp = t >> 5;
    int x = s;
#pragma unroll
    for (int off = 1; off < 32; off <<= 1) {
        int y = __shfl_up_sync(0xffffffffu, x, off);
        if (lane >= off) x += y;
    }
    if (lane == 31) warp_sums[warp] = x;
    __syncthreads();
    if (warp == 0 && lane < 16) {
        int y = warp_sums[lane];
#pragma unroll
        for (int off = 1; off < 16; off <<= 1) {
            int z = __shfl_up_sync(0x0000ffffu, y, off);
            if (lane >= off) y += z;
        }
        warp_sums[lane] = y;
    }
    __syncthreads();
    int prefix = x - s + (warp ? warp_sums[warp - 1] : 0);
#pragma unroll
    for (int i = 0; i < 32; i++) g_rowstart[base + i] = prefix + local[i];
    if (t == 511) g_rowstart[VV] = prefix + s;
}

__global__ void k_scatter(const int* __restrict__ rows, const int* __restrict__ cols,
                          const float* __restrict__ vals) {
    int e = blockIdx.x * 256 + threadIdx.x;
    int r = rows[e];
    int pos = g_rowstart[r] + atomicAdd(&g_cursor[r], 1);
    g_edges[pos] = make_int2(cols[e], __float_as_int(vals[e]));
}

// ---------------- SpMM (CSR, warp per row, 2-way ILP) ----------------
// dst[row][:] = c * (L @ src)[row][:] - (prev ? prev[row][:] : 0)
__global__ void k_spmm(const float* __restrict__ src, const float* __restrict__ prev,
                       float* __restrict__ dst, float c) {
    int warp = threadIdx.x >> 5, lane = threadIdx.x & 31;
    int row = blockIdx.x * 8 + warp;
    int s = g_rowstart[row], e = g_rowstart[row + 1];
    float a0 = 0.f, a1 = 0.f, b0 = 0.f, b1 = 0.f;
    int i = s;
    for (; i + 1 < e; i += 2) {
        int2 e0 = g_edges[i];
        int2 e1 = g_edges[i + 1];
        const float* p0 = src + e0.x * BB;
        const float* p1 = src + e1.x * BB;
        float v0 = __int_as_float(e0.y);
        float v1 = __int_as_float(e1.y);
        a0 += v0 * p0[lane];
        a1 += v0 * p0[lane + 32];
        b0 += v1 * p1[lane];
        b1 += v1 * p1[lane + 32];
    }
    if (i < e) {
        int2 e0 = g_edges[i];
        const float* p0 = src + e0.x * BB;
        float v0 = __int_as_float(e0.y);
        a0 += v0 * p0[lane];
        a1 += v0 * p0[lane + 32];
    }
    a0 += b0; a1 += b1;
    float p0 = prev ? prev[row * BB + lane] : 0.f;
    float p1 = prev ? prev[row * BB + lane + 32] : 0.f;
    dst[row * BB + lane]      = c * a0 - p0;
    dst[row * BB + lane + 32] = c * a1 - p1;
}

// ---------------- cheby combine + relu + maxpool(8) ----------------
__global__ void k_cheby(const float* __restrict__ w, const float* __restrict__ bias) {
    __shared__ float tile[6][8][64];
    int vp = blockIdx.x;
    int t = threadIdx.x;
    for (int idx = t; idx < 6 * 8 * 64; idx += 256) {
        int k = idx >> 9;
        int rem = idx & 511;
        int p = rem >> 6;
        int b = rem & 63;
        tile[k][p][b] = g_xs[k * (VV * BB) + (vp * 8 + p) * BB + b];
    }
    __syncthreads();
    int f = t & 31, bg = t >> 5;
    float wr[6];
#pragma unroll
    for (int k = 0; k < 6; k++) wr[k] = w[f * 6 + k];
    float bf = bias[f];
    for (int bb = 0; bb < 8; bb++) {
        int b = bg * 8 + bb;
        float m = -1e30f;
#pragma unroll
        for (int p = 0; p < 8; p++) {
            float s = bf;
#pragma unroll
            for (int k = 0; k < 6; k++) s += tile[k][p][b] * wr[k];
            m = fmaxf(m, s);
        }
        g_pooled[b * FC1FIN + vp * 32 + f] = fmaxf(m, 0.f);
    }
}

// ---------------- init all atomic-accumulated C buffers with bias ----------------
// out_hid[64][512], xn1[64][1024], xd[64][512], xn[64][512]
__global__ void k_initall(float* __restrict__ out_hid,
                          const float* __restrict__ fc1_b,
                          const float* __restrict__ nn1_b,
                          const float* __restrict__ fc2_b,
                          const float* __restrict__ nn2_b) {
    int i = blockIdx.x * 256 + threadIdx.x;   // [0, 64*2560)
    float* xn1; asm("cvta.global.u64 %0, g_xn1;" : "=l"(xn1));
    float* xd;  asm("cvta.global.u64 %0, g_xd;"  : "=l"(xd));
    float* xn;  asm("cvta.global.u64 %0, g_xn;"  : "=l"(xn));
    if (i < 64 * 512) {
        out_hid[i] = fc1_b[i & 511];
    } else if (i < 64 * 512 + 64 * 1024) {
        int j = i - 64 * 512;
        xn1[j] = nn1_b[j & 1023];
    } else if (i < 64 * 512 + 64 * 1024 + 64 * 512) {
        int j = i - (64 * 512 + 64 * 1024);
        xd[j] = fc2_b[j & 511];
    } else {
        int j = i - (64 * 512 + 64 * 1024 + 64 * 512);
        xn[j] = nn2_b[j & 511];
    }
}

__global__ void k_relu(float* __restrict__ C) {
    int i = blockIdx.x * 256 + threadIdx.x;
    C[i] = fmaxf(C[i], 0.f);
}

// C[64,N] (+)= A[64,K] * W[N,K]^T
// split-K via grid.y + atomic accumulate; grid.y==1 -> direct store of bias+acc.
// arelu: apply relu to A elements on load.
__global__ void k_gemm(const float* __restrict__ A, const float* __restrict__ W,
                       float* __restrict__ C, const float* __restrict__ bias,
                       int K, int N, int kchunk, int arelu, int direct) {
    __shared__ unsigned As[64][36];
    __shared__ unsigned Ws[64][36];
    int t = threadIdx.x;
    int lane = t & 31, warp = t >> 5;
    int jt = blockIdx.x * 64;
    int k0 = blockIdx.y * kchunk;
    int kend = k0 + kchunk;
    int bq = warp & 3;   // b-row block (*16)
    int jh = warp >> 2;  // j-col block (*32)
    float acc[4][4] = {};

    int row0 = t >> 3,        q0 = t & 7;
    int row1 = (t + 256) >> 3, q1 = t & 7;
    const float* Ap0 = A + row0 * K + q0 * 4;
    const float* Ap1 = A + row1 * K + q1 * 4;
    const float* Wp0 = W + (jt + row0) * K + q0 * 4;
    const float* Wp1 = W + (jt + row1) * K + q1 * 4;

    float4 va0 = *reinterpret_cast<const float4*>(Ap0 + k0);
    float4 va1 = *reinterpret_cast<const float4*>(Ap1 + k0);
    float4 vw0 = *reinterpret_cast<const float4*>(Wp0 + k0);
    float4 vw1 = *reinterpret_cast<const float4*>(Wp1 + k0);

    for (int kt = k0; kt < kend; kt += 32) {
        if (arelu) {
            va0.x = fmaxf(va0.x, 0.f); va0.y = fmaxf(va0.y, 0.f);
            va0.z = fmaxf(va0.z, 0.f); va0.w = fmaxf(va0.w, 0.f);
            va1.x = fmaxf(va1.x, 0.f); va1.y = fmaxf(va1.y, 0.f);
            va1.z = fmaxf(va1.z, 0.f); va1.w = fmaxf(va1.w, 0.f);
        }
        As[row0][q0 * 4 + 0] = f2tf(va0.x);
        As[row0][q0 * 4 + 1] = f2tf(va0.y);
        As[row0][q0 * 4 + 2] = f2tf(va0.z);
        As[row0][q0 * 4 + 3] = f2tf(va0.w);
        As[row1][q1 * 4 + 0] = f2tf(va1.x);
        As[row1][q1 * 4 + 1] = f2tf(va1.y);
        As[row1][q1 * 4 + 2] = f2tf(va1.z);
        As[row1][q1 * 4 + 3] = f2tf(va1.w);
        Ws[row0][q0 * 4 + 0] = f2tf(vw0.x);
        Ws[row0][q0 * 4 + 1] = f2tf(vw0.y);
        Ws[row0][q0 * 4 + 2] = f2tf(vw0.z);
        Ws[row0][q0 * 4 + 3] = f2tf(vw0.w);
        Ws[row1][q1 * 4 + 0] = f2tf(vw1.x);
        Ws[row1][q1 * 4 + 1] = f2tf(vw1.y);
        Ws[row1][q1 * 4 + 2] = f2tf(vw1.z);
        Ws[row1][q1 * 4 + 3] = f2tf(vw1.w);
        __syncthreads();

        int kn = kt + 32;
        if (kn < kend) {   // prefetch next tile while MMAs run
            va0 = *reinterpret_cast<const float4*>(Ap0 + kn);
            va1 = *reinterpret_cast<const float4*>(Ap1 + kn);
            vw0 = *reinterpret_cast<const float4*>(Wp0 + kn);
            vw1 = *reinterpret_cast<const float4*>(Wp1 + kn);
        }

#pragma unroll
        for (int ks = 0; ks < 4; ks++) {
            int kk = ks * 8;
            unsigned a0 = As[bq * 16 + (lane >> 2)][kk + (lane & 3)];
            unsigned a1 = As[bq * 16 + (lane >> 2) + 8][kk + (lane & 3)];
            unsigned a2 = As[bq * 16 + (lane >> 2)][kk + (lane & 3) + 4];
            unsigned a3 = As[bq * 16 + (lane >> 2) + 8][kk + (lane & 3) + 4];
#pragma unroll
            for (int nf = 0; nf < 4; nf++) {
                int nrow = jh * 32 + nf * 8 + (lane >> 2);
                unsigned b0 = Ws[nrow][kk + (lane & 3)];
                unsigned b1 = Ws[nrow][kk + (lane & 3) + 4];
                mma_tf32(acc[nf], a0, a1, a2, a3, b0, b1);
            }
        }
        __syncthreads();
    }
    int r0 = bq * 16 + (lane >> 2);
    if (direct) {
#pragma unroll
        for (int nf = 0; nf < 4; nf++) {
            int c0 = jt + jh * 32 + nf * 8 + 2 * (lane & 3);
            float bz0 = bias[c0], bz1 = bias[c0 + 1];
            C[r0 * N + c0]           = bz0 + acc[nf][0];
            C[r0 * N + c0 + 1]       = bz1 + acc[nf][1];
            C[(r0 + 8) * N + c0]     = bz0 + acc[nf][2];
            C[(r0 + 8) * N + c0 + 1] = bz1 + acc[nf][3];
        }
    } else {
#pragma unroll
        for (int nf = 0; nf < 4; nf++) {
            int c0 = jt + jh * 32 + nf * 8 + 2 * (lane & 3);
            atomicAdd(&C[r0 * N + c0],           acc[nf][0]);
            atomicAdd(&C[r0 * N + c0 + 1],       acc[nf][1]);
            atomicAdd(&C[(r0 + 8) * N + c0],     acc[nf][2]);
            atomicAdd(&C[(r0 + 8) * N + c0 + 1], acc[nf][3]);
        }
    }
}

// ---------------- sum2 + log_softmax (relu applied to xn on load) ----------------
__global__ void k_sum2(const float* __restrict__ xh, const float* __restrict__ xn,
                       const float* __restrict__ w, const float* __restrict__ bias,
                       float* __restrict__ out) {
    int b = blockIdx.x;
    int t = threadIdx.x, lane = t & 31, warp = t >> 5;
    __shared__ float red[10];
    for (int o = warp; o < 10; o += 8) {
        float p = 0.f;
        for (int k = lane; k < 1024; k += 32) {
            float xv = (k < 512) ? xh[b * 512 + k] : fmaxf(xn[b * 512 + k - 512], 0.f);
            p += xv * w[o * 1024 + k];
        }
#pragma unroll
        for (int off = 16; off; off >>= 1) p += __shfl_down_sync(0xffffffffu, p, off);
        if (lane == 0) red[o] = p + bias[o];
    }
    __syncthreads();
    if (t == 0) {
        float m = -1e30f;
        for (int o = 0; o < 10; o++) m = fmaxf(m, red[o]);
        float s = 0.f;
        for (int o = 0; o < 10; o++) s += expf(red[o] - m);
        float lse = m + logf(s);
        for (int o = 0; o < 10; o++) out[b * 10 + o] = red[o] - lse;
    }
}

// ---------------- launch ----------------
extern "C" void kernel_launch(void* const* d_in, const int* in_sizes, int n_in,
                              void* d_out, int out_size) {
    const float* x_in   = (const float*)d_in[0];
    const float* L_vals = (const float*)d_in[1];
    const float* cl1_w  = (const float*)d_in[2];
    const float* cl1_b  = (const float*)d_in[3];
    const float* fc1_w  = (const float*)d_in[4];
    const float* fc1_b  = (const float*)d_in[5];
    const float* fc2_w  = (const float*)d_in[6];
    const float* fc2_b  = (const float*)d_in[7];
    const float* fc3_w  = (const float*)d_in[8];
    const float* fc3_b  = (const float*)d_in[9];
    const float* nn1_w  = (const float*)d_in[10];
    const float* nn1_b  = (const float*)d_in[11];
    const float* nn2_w  = (const float*)d_in[12];
    const float* nn2_b  = (const float*)d_in[13];
    const float* sum2_w = (const float*)d_in[14];
    const float* sum2_b = (const float*)d_in[15];
    const int*   L_rows = (const int*)d_in[16];
    const int*   L_cols = (const int*)d_in[17];

    float* out = (float*)d_out;
    float* out_dec = out;                    // [64,16384]
    float* out_hid = out + 64 * 16384;       // [64,512]
    float* out_lp  = out_hid + 64 * 512;     // [64,10]

    float* xs;     cudaGetSymbolAddress((void**)&xs, g_xs);
    float* pooled; cudaGetSymbolAddress((void**)&pooled, g_pooled);
    int*   counts; cudaGetSymbolAddress((void**)&counts, g_counts);
    int*   cursor; cudaGetSymbolAddress((void**)&cursor, g_cursor);
    float* xd;     cudaGetSymbolAddress((void**)&xd, g_xd);
    float* xn1;    cudaGetSymbolAddress((void**)&xn1, g_xn1);
    float* xn;     cudaGetSymbolAddress((void**)&xn, g_xn);

    const int VB = VV * BB;

    // x0 = x_in^T
    k_transpose<<<dim3(VV / 32, 2), dim3(32, 8)>>>(x_in, xs);

    // CSR build
    cudaMemsetAsync(counts, 0, VV * sizeof(int));
    cudaMemsetAsync(cursor, 0, VV * sizeof(int));
    k_hist<<<EE / 512, 256>>>(L_rows);
    k_scan<<<1, 512>>>();
    k_scatter<<<EE / 256, 256>>>(L_rows, L_cols, L_vals);

    // cheby recurrence
    k_spmm<<<VV / 8, 256>>>(xs, nullptr, xs + VB, 1.f);
    for (int k = 2; k < KCH; k++)
        k_spmm<<<VV / 8, 256>>>(xs + (k - 1) * VB, xs + (k - 2) * VB, xs + k * VB, 2.f);

    // conv-combine + relu + maxpool -> pooled [64][65536]
    k_cheby<<<VV / 8, 256>>>(cl1_w, cl1_b);

    // init bias for all atomic-accumulated outputs (one launch)
    k_initall<<<64 * 2560 / 256, 256>>>(out_hid, fc1_b, nn1_b, fc2_b, nn2_b);

    // fc1 -> x_hidden (in d_out), split-K 64
    k_gemm<<<dim3(512 / 64, 64), 256>>>(pooled, fc1_w, out_hid, nullptr, 65536, 512, 1024, 0, 0);
    // nn1 -> xn1, split-K 32
    k_gemm<<<dim3(1024 / 64, 32), 256>>>(x_in, nn1_w, xn1, nullptr, 16384, 1024, 512, 0, 0);

    // relu only for out_hid (it is itself an output)
    k_relu<<<64 * 512 / 256, 256>>>(out_hid);

    // fc2 -> xd (A already relu'd)
    k_gemm<<<dim3(512 / 64, 8), 256>>>(out_hid, fc2_w, xd, nullptr, 512, 512, 64, 0, 0);
    // nn2 -> xn (relu fused on A=xn1)
    k_gemm<<<dim3(512 / 64, 8), 256>>>(xn1, nn2_w, xn, nullptr, 1024, 512, 128, 1, 0);
    // fc3 -> x_decode (relu fused on A=xd, direct store with bias)
    k_gemm<<<dim3(16384 / 64, 1), 256>>>(xd, fc3_w, out_dec, fc3_b, 512, 16384, 512, 1, 1);

    // sum2 + log_softmax (relu fused on xn)
    k_sum2<<<64, 256>>>(out_hid, xn, sum2_w, sum2_b, out_lp);
}